// round 12
// baseline (speedup 1.0000x reference)
#include <cuda_runtime.h>

#define D_ 4
#define R_ 32
#define F_ 8
#define U_ 64
#define B_ 512

typedef unsigned long long ull;

// ---------- packed f32x2 helpers (SASS FFMA2) ----------
static __device__ __forceinline__ ull pk2(float lo, float hi) {
    ull r; asm("mov.b64 %0, {%1, %2};" : "=l"(r) : "f"(lo), "f"(hi)); return r;
}
static __device__ __forceinline__ void upk2(ull v, float& lo, float& hi) {
    asm("mov.b64 {%0, %1}, %2;" : "=f"(lo), "=f"(hi) : "l"(v));
}
static __device__ __forceinline__ ull fma2_(ull a, ull b, ull c) {
    ull d; asm("fma.rn.f32x2 %0, %1, %2, %3;" : "=l"(d) : "l"(a), "l"(b), "l"(c)); return d;
}
static __device__ __forceinline__ ull mul2_(ull a, ull b) {
    ull d; asm("mul.rn.f32x2 %0, %1, %2;" : "=l"(d) : "l"(a), "l"(b)); return d;
}
static __device__ __forceinline__ ull add2_(ull a, ull b) {
    ull d; asm("add.rn.f32x2 %0, %1, %2;" : "=l"(d) : "l"(a), "l"(b)); return d;
}

// Pair-merged products: g_KK[u][p][c=(d0*4+d1)][j*32+k], and its transpose
// g_KKT[u][p][c][k*32+j].
__device__ float g_KK [U_ * 4 * 16 * 1024];   // 16 MB
__device__ float g_KKT[U_ * 4 * 16 * 1024];   // 16 MB

// ---------------------------------------------------------------------------
// Precompute: 256 blocks = (u,p), 512 threads = 16 warps, warp w computes c=w.
// Writes both KK (row-major) and KKT (transposed, via smem transpose).
// (identical to the proven R10 version)
// ---------------------------------------------------------------------------
__global__ __launch_bounds__(512) void kk_precompute(const float* __restrict__ K) {
    extern __shared__ float ps[];
    float* As = ps;            // 4 * 1056 (pitch 33)
    float* Bs = ps + 4224;     // 4 * 1024
    float* Ts = ps + 8320;     // 16 * 1056 (per-warp transpose staging)
    const int u = blockIdx.x >> 2;
    const int p = blockIdx.x & 3;
    const int tid = threadIdx.x;

    for (int d = 0; d < 4; d++)
        for (int e = tid; e < 1024; e += 512) {
            As[d * 1056 + (e >> 5) * 33 + (e & 31)] =
                K[((d * 1024 + e) * 8 + 2 * p) * 64 + u];
            Bs[d * 1024 + e] = K[((d * 1024 + e) * 8 + 2 * p + 1) * 64 + u];
        }
    __syncthreads();

    const int c = tid >> 5, lane = tid & 31;
    const int d0 = c >> 2, d1 = c & 3;
    ull acc[16];
    #pragma unroll
    for (int q = 0; q < 16; q++) acc[q] = 0ull;
    const float* arow = &As[d0 * 1056 + lane * 33];
    const ulonglong2* bmat = (const ulonglong2*)(Bs + d1 * 1024);
    #pragma unroll
    for (int j = 0; j < 32; j++) {
        const ull a2 = pk2(arow[j], arow[j]);
        #pragma unroll
        for (int q = 0; q < 8; q++) {
            const ulonglong2 bv = bmat[j * 8 + q];   // broadcast
            acc[2 * q]     = fma2_(a2, bv.x, acc[2 * q]);
            acc[2 * q + 1] = fma2_(a2, bv.y, acc[2 * q + 1]);
        }
    }
    float f[32];
    #pragma unroll
    for (int q = 0; q < 16; q++) upk2(acc[q], f[2 * q], f[2 * q + 1]);
    {
        float4* dst = (float4*)(g_KK + (((u * 4 + p) * 16 + c) * 1024) + lane * 32);
        #pragma unroll
        for (int q = 0; q < 8; q++) {
            float4 o; o.x = f[4*q]; o.y = f[4*q+1]; o.z = f[4*q+2]; o.w = f[4*q+3];
            dst[q] = o;
        }
    }
    float* Tw = Ts + c * 1056;
    #pragma unroll
    for (int k = 0; k < 32; k++) Tw[lane * 33 + k] = f[k];
    __syncwarp();
    float* kt = g_KKT + (((u * 4 + p) * 16 + c) * 1024);
    #pragma unroll
    for (int i = 0; i < 32; i++)
        kt[i * 32 + lane] = Tw[lane * 33 + i];
}

// ---------------------------------------------------------------------------
// Main. Block = 256 threads = 8 warps, one u, 8 b (warp w owns b = b0+w).
// Smem (floats): W[512] | SL[8*1152] | SR[8*1152]  = 75776 B -> 3 CTAs/SM.
// Register-lean variant of the R10 structure targeting 85 regs/thread.
// ---------------------------------------------------------------------------
#define PITCH 36
#define SLOT  1152
#define OFF_SL  512
#define OFF_SR  (OFF_SL + 8 * SLOT)
#define SMEM_FLOATS (OFF_SR + 8 * SLOT)

// Build one stage for all 8 b's; 256 threads, thread e owns element
// (j = e>>3, k4 = e&7). Single-pass kk[16]; W scalars packed inline (one q
// live at a time); result written immediately per b (no acc array).
template <int T>
static __device__ __forceinline__ void build_stage(int u, int p, int e,
                                                   const float* Wsm, float* dst) {
    const ulonglong2* base = (const ulonglong2*)(
        (T ? g_KKT : g_KK) + (size_t)((u * 4 + p) * 16) * 1024);
    ulonglong2 kk[16];
    #pragma unroll
    for (int cc = 0; cc < 16; cc++) kk[cc] = base[cc * 256 + e];   // coalesced
    const int j = e >> 3, k4 = e & 7;
    #pragma unroll 2
    for (int b = 0; b < 8; b++) {
        const float4* wp = (const float4*)(Wsm + (b * 4 + p) * 16);
        float4 wA = wp[0], wB = wp[1];
        ull q;
        q = pk2(wA.x, wA.x);
        ull ax0 = mul2_(q, kk[0].x),  ay0 = mul2_(q, kk[0].y);
        q = pk2(wA.y, wA.y);
        ull ax1 = mul2_(q, kk[1].x),  ay1 = mul2_(q, kk[1].y);
        q = pk2(wA.z, wA.z); ax0 = fma2_(q, kk[2].x, ax0);  ay0 = fma2_(q, kk[2].y, ay0);
        q = pk2(wA.w, wA.w); ax1 = fma2_(q, kk[3].x, ax1);  ay1 = fma2_(q, kk[3].y, ay1);
        wA = wp[2];
        q = pk2(wB.x, wB.x); ax0 = fma2_(q, kk[4].x, ax0);  ay0 = fma2_(q, kk[4].y, ay0);
        q = pk2(wB.y, wB.y); ax1 = fma2_(q, kk[5].x, ax1);  ay1 = fma2_(q, kk[5].y, ay1);
        q = pk2(wB.z, wB.z); ax0 = fma2_(q, kk[6].x, ax0);  ay0 = fma2_(q, kk[6].y, ay0);
        q = pk2(wB.w, wB.w); ax1 = fma2_(q, kk[7].x, ax1);  ay1 = fma2_(q, kk[7].y, ay1);
        wB = wp[3];
        q = pk2(wA.x, wA.x); ax0 = fma2_(q, kk[8].x, ax0);  ay0 = fma2_(q, kk[8].y, ay0);
        q = pk2(wA.y, wA.y); ax1 = fma2_(q, kk[9].x, ax1);  ay1 = fma2_(q, kk[9].y, ay1);
        q = pk2(wA.z, wA.z); ax0 = fma2_(q, kk[10].x, ax0); ay0 = fma2_(q, kk[10].y, ay0);
        q = pk2(wA.w, wA.w); ax1 = fma2_(q, kk[11].x, ax1); ay1 = fma2_(q, kk[11].y, ay1);
        q = pk2(wB.x, wB.x); ax0 = fma2_(q, kk[12].x, ax0); ay0 = fma2_(q, kk[12].y, ay0);
        q = pk2(wB.y, wB.y); ax1 = fma2_(q, kk[13].x, ax1); ay1 = fma2_(q, kk[13].y, ay1);
        q = pk2(wB.z, wB.z); ax0 = fma2_(q, kk[14].x, ax0); ay0 = fma2_(q, kk[14].y, ay0);
        q = pk2(wB.w, wB.w); ax1 = fma2_(q, kk[15].x, ax1); ay1 = fma2_(q, kk[15].y, ay1);
        const ull sx = add2_(ax0, ax1), sy = add2_(ay0, ay1);
        float4 o;
        upk2(sx, o.x, o.y); upk2(sy, o.z, o.w);
        *(float4*)(dst + b * SLOT + j * PITCH + 4 * k4) = o;
    }
}

// Register-tiled 32x32x32 matmul, low-staging variant: B operands loaded per
// kp (8 regs live) instead of all 32. Lane (r = lane>>2, c = lane&3):
// rows {r,r+8,r+16,r+24} x cols {8c..8c+7}.
static __device__ __forceinline__ void mmk(const float* A, const float* B,
                                           int r, int c, ull acc[16]) {
    #pragma unroll
    for (int i = 0; i < 16; i++) acc[i] = 0ull;
    #pragma unroll
    for (int k4 = 0; k4 < 8; k4++) {
        float4 av[4];
        #pragma unroll
        for (int rho = 0; rho < 4; rho++)
            av[rho] = *(const float4*)(A + (r + 8 * rho) * PITCH + 4 * k4);
        #pragma unroll
        for (int kp = 0; kp < 4; kp++) {
            const ulonglong2 b0 = *(const ulonglong2*)(B + (4 * k4 + kp) * PITCH + 8 * c);
            const ulonglong2 b1 = *(const ulonglong2*)(B + (4 * k4 + kp) * PITCH + 8 * c + 4);
            #pragma unroll
            for (int rho = 0; rho < 4; rho++) {
                const float a = ((const float*)&av[rho])[kp];
                const ull a2 = pk2(a, a);
                acc[rho * 4 + 0] = fma2_(a2, b0.x, acc[rho * 4 + 0]);
                acc[rho * 4 + 1] = fma2_(a2, b0.y, acc[rho * 4 + 1]);
                acc[rho * 4 + 2] = fma2_(a2, b1.x, acc[rho * 4 + 2]);
                acc[rho * 4 + 3] = fma2_(a2, b1.y, acc[rho * 4 + 3]);
            }
        }
    }
}

__global__ __launch_bounds__(256, 3) void ring_main(const float* __restrict__ X,
                                                    float* __restrict__ out) {
    extern __shared__ float smem[];
    float* Wsm = smem;
    float* SL  = smem + OFF_SL;
    float* SR  = smem + OFF_SR;

    const int tid = threadIdx.x, w = tid >> 5, lane = tid & 31;
    const int r = lane >> 2, c = lane & 3;
    const int u = blockIdx.x >> 6;
    const int b0 = (blockIdx.x & 63) * 8;

    // W[b][p][c=(d0,d1)] = x[2p,d0] * x[2p+1,d1], straight from global X
    #pragma unroll
    for (int i = tid; i < 512; i += 256) {
        const int bb = i >> 6, pp = (i >> 4) & 3, cc = i & 15;
        Wsm[i] = X[(b0 + bb) * 32 + 8 * pp + (cc >> 2)] *
                 X[(b0 + bb) * 32 + 8 * pp + 4 + (cc & 3)];
    }
    __syncthreads();

    // ---- builds phase 1: S0 -> SL, S1 -> SR (normal orientation)
    build_stage<0>(u, 0, tid, Wsm, SL);
    build_stage<0>(u, 1, tid, Wsm, SR);
    __syncthreads();

    // ---- mm1: A = S0 @ S1, kept in registers
    ull acc1[16];
    mmk(SL + w * SLOT, SR + w * SLOT, r, c, acc1);
    __syncthreads();   // all warps done reading SL/SR

    // ---- builds phase 2: S2^T -> SL, S3^T -> SR (from g_KKT)
    build_stage<1>(u, 2, tid, Wsm, SL);
    build_stage<1>(u, 3, tid, Wsm, SR);
    __syncthreads();

    // ---- mm2: BT = S3^T @ S2^T = (S2 S3)^T ; out = sum A .* BT
    {
        ull acc2[16];
        mmk(SR + w * SLOT, SL + w * SLOT, r, c, acc2);
        ull t = 0ull;
        #pragma unroll
        for (int i = 0; i < 16; i++) t = fma2_(acc1[i], acc2[i], t);
        float tl, th; upk2(t, tl, th);
        float pacc = tl + th;
        #pragma unroll
        for (int o = 16; o; o >>= 1)
            pacc += __shfl_xor_sync(0xffffffffu, pacc, o);
        if (lane == 0) out[(b0 + w) * 64 + u] = pacc;
    }
}

extern "C" void kernel_launch(void* const* d_in, const int* in_sizes, int n_in,
                              void* d_out, int out_size) {
    const float* X = (const float*)d_in[0];
    const float* K = (const float*)d_in[1];
    if (in_sizes[0] != B_ * F_ * D_) {
        X = (const float*)d_in[1];
        K = (const float*)d_in[0];
    }
    const int pre_smem = (4224 + 4096 + 16 * 1056) * 4;
    cudaFuncSetAttribute(kk_precompute, cudaFuncAttributeMaxDynamicSharedMemorySize,
                         pre_smem);
    cudaFuncSetAttribute(ring_main, cudaFuncAttributeMaxDynamicSharedMemorySize,
                         SMEM_FLOATS * 4);
    kk_precompute<<<256, 512, pre_smem>>>(K);
    ring_main<<<64 * 64, 256, SMEM_FLOATS * 4>>>(X, (float*)d_out);
}

// round 13
// speedup vs baseline: 1.5147x; 1.5147x over previous
#include <cuda_runtime.h>

#define D_ 4
#define R_ 32
#define F_ 8
#define U_ 64
#define B_ 512

typedef unsigned long long ull;

// ---------- packed f32x2 helpers (SASS FFMA2) ----------
static __device__ __forceinline__ ull pk2(float lo, float hi) {
    ull r; asm("mov.b64 %0, {%1, %2};" : "=l"(r) : "f"(lo), "f"(hi)); return r;
}
static __device__ __forceinline__ void upk2(ull v, float& lo, float& hi) {
    asm("mov.b64 {%0, %1}, %2;" : "=f"(lo), "=f"(hi) : "l"(v));
}
static __device__ __forceinline__ ull fma2_(ull a, ull b, ull c) {
    ull d; asm("fma.rn.f32x2 %0, %1, %2, %3;" : "=l"(d) : "l"(a), "l"(b), "l"(c)); return d;
}
static __device__ __forceinline__ ull mul2_(ull a, ull b) {
    ull d; asm("mul.rn.f32x2 %0, %1, %2;" : "=l"(d) : "l"(a), "l"(b)); return d;
}
static __device__ __forceinline__ ull add2_(ull a, ull b) {
    ull d; asm("add.rn.f32x2 %0, %1, %2;" : "=l"(d) : "l"(a), "l"(b)); return d;
}

// Pair-merged products. Only the orientation each stage needs is materialized:
//   p in {0,1}: g_KK [u][p][c][j*32+k]   (row-major)
//   p in {2,3}: g_KKT[u][p][c][k*32+j]   (transposed)
// Both arrays keep the full [u][4][16][1024] indexing so ring_main's address
// math is unchanged; the unused halves are simply never written or read.
__device__ float g_KK [U_ * 4 * 16 * 1024];   // 16 MB
__device__ float g_KKT[U_ * 4 * 16 * 1024];   // 16 MB

// ---------------------------------------------------------------------------
// Precompute: 256 blocks = (u,p), 512 threads = 16 warps, warp w computes c=w.
// p<2 -> write KK row-major only. p>=2 -> write KKT (via smem transpose) only.
// ---------------------------------------------------------------------------
__global__ __launch_bounds__(512) void kk_precompute(const float* __restrict__ K) {
    extern __shared__ float ps[];
    float* As = ps;            // 4 * 1056 (pitch 33)
    float* Bs = ps + 4224;     // 4 * 1024
    float* Ts = ps + 8320;     // 16 * 1056 (per-warp transpose staging, p>=2 only)
    const int u = blockIdx.x >> 2;
    const int p = blockIdx.x & 3;
    const int tid = threadIdx.x;

    for (int d = 0; d < 4; d++)
        for (int e = tid; e < 1024; e += 512) {
            As[d * 1056 + (e >> 5) * 33 + (e & 31)] =
                K[((d * 1024 + e) * 8 + 2 * p) * 64 + u];
            Bs[d * 1024 + e] = K[((d * 1024 + e) * 8 + 2 * p + 1) * 64 + u];
        }
    __syncthreads();

    const int c = tid >> 5, lane = tid & 31;
    const int d0 = c >> 2, d1 = c & 3;
    ull acc[16];
    #pragma unroll
    for (int q = 0; q < 16; q++) acc[q] = 0ull;
    const float* arow = &As[d0 * 1056 + lane * 33];
    const ulonglong2* bmat = (const ulonglong2*)(Bs + d1 * 1024);
    #pragma unroll
    for (int j = 0; j < 32; j++) {
        const ull a2 = pk2(arow[j], arow[j]);
        #pragma unroll
        for (int q = 0; q < 8; q++) {
            const ulonglong2 bv = bmat[j * 8 + q];   // broadcast
            acc[2 * q]     = fma2_(a2, bv.x, acc[2 * q]);
            acc[2 * q + 1] = fma2_(a2, bv.y, acc[2 * q + 1]);
        }
    }
    float f[32];
    #pragma unroll
    for (int q = 0; q < 16; q++) upk2(acc[q], f[2 * q], f[2 * q + 1]);

    if (p < 2) {
        // row-major write (lane = row), coalesced float4
        float4* dst = (float4*)(g_KK + (((u * 4 + p) * 16 + c) * 1024) + lane * 32);
        #pragma unroll
        for (int q = 0; q < 8; q++) {
            float4 o; o.x = f[4*q]; o.y = f[4*q+1]; o.z = f[4*q+2]; o.w = f[4*q+3];
            dst[q] = o;
        }
    } else {
        // transposed write via smem staging (pitch 33, conflict-free both ways)
        float* Tw = Ts + c * 1056;
        #pragma unroll
        for (int k = 0; k < 32; k++) Tw[lane * 33 + k] = f[k];
        __syncwarp();
        float* kt = g_KKT + (((u * 4 + p) * 16 + c) * 1024);
        #pragma unroll
        for (int i = 0; i < 32; i++)
            kt[i * 32 + lane] = Tw[lane * 33 + i];   // coalesced STG.32
    }
}

// ---------------------------------------------------------------------------
// Main (UNCHANGED from the proven R10 version, 195.3 us).
// Block = 256 threads = 8 warps, one u, 8 b (warp w owns b = b0+w).
// Smem (floats): W[512] | SL[8*1152] | SR[8*1152]   (~74 KB, 2 CTAs/SM)
// All S buffers pitch 36, float4 rows. S2/S3 are built TRANSPOSED from g_KKT.
// out = sum_{i,j} A[i,j] * BT[i,j],  A = S0@S1 (regs), BT = S3T@S2T (regs).
// ---------------------------------------------------------------------------
#define PITCH 36
#define SLOT  1152
#define OFF_SL  512
#define OFF_SR  (OFF_SL + 8 * SLOT)
#define SMEM_FLOATS (OFF_SR + 8 * SLOT)

template <int T>
static __device__ __forceinline__ void build_stage(int u, int p, int e,
                                                   const float* Wsm, float* dst) {
    const ulonglong2* base = (const ulonglong2*)(
        (T ? g_KKT : g_KK) + (size_t)((u * 4 + p) * 16) * 1024);
    ull acc[8][2];
    #pragma unroll
    for (int h = 0; h < 2; h++) {
        ulonglong2 kk[8];
        #pragma unroll
        for (int cc = 0; cc < 8; cc++) kk[cc] = base[(h * 8 + cc) * 256 + e];
        #pragma unroll
        for (int b = 0; b < 8; b++) {
            const float4* wp = (const float4*)(Wsm + (b * 4 + p) * 16 + h * 8);
            const float4 wa = wp[0], wb = wp[1];     // broadcast
            const ull q0 = pk2(wa.x, wa.x), q1 = pk2(wa.y, wa.y);
            const ull q2 = pk2(wa.z, wa.z), q3 = pk2(wa.w, wa.w);
            const ull q4 = pk2(wb.x, wb.x), q5 = pk2(wb.y, wb.y);
            const ull q6 = pk2(wb.z, wb.z), q7 = pk2(wb.w, wb.w);
            ull ax0 = mul2_(q0, kk[0].x), ay0 = mul2_(q0, kk[0].y);
            ull ax1 = mul2_(q1, kk[1].x), ay1 = mul2_(q1, kk[1].y);
            ax0 = fma2_(q2, kk[2].x, ax0);  ay0 = fma2_(q2, kk[2].y, ay0);
            ax1 = fma2_(q3, kk[3].x, ax1);  ay1 = fma2_(q3, kk[3].y, ay1);
            ax0 = fma2_(q4, kk[4].x, ax0);  ay0 = fma2_(q4, kk[4].y, ay0);
            ax1 = fma2_(q5, kk[5].x, ax1);  ay1 = fma2_(q5, kk[5].y, ay1);
            ax0 = fma2_(q6, kk[6].x, ax0);  ay0 = fma2_(q6, kk[6].y, ay0);
            ax1 = fma2_(q7, kk[7].x, ax1);  ay1 = fma2_(q7, kk[7].y, ay1);
            const ull sx = add2_(ax0, ax1), sy = add2_(ay0, ay1);
            if (h == 0) { acc[b][0] = sx; acc[b][1] = sy; }
            else { acc[b][0] = add2_(acc[b][0], sx); acc[b][1] = add2_(acc[b][1], sy); }
        }
    }
    const int j = e >> 3, k4 = e & 7;
    #pragma unroll
    for (int b = 0; b < 8; b++) {
        float4 o;
        upk2(acc[b][0], o.x, o.y); upk2(acc[b][1], o.z, o.w);
        *(float4*)(dst + b * SLOT + j * PITCH + 4 * k4) = o;
    }
}

static __device__ __forceinline__ void mmk(const float* A, const float* B,
                                           int r, int c, ull acc[16]) {
    #pragma unroll
    for (int i = 0; i < 16; i++) acc[i] = 0ull;
    #pragma unroll
    for (int k4 = 0; k4 < 8; k4++) {
        float4 av[4];
        #pragma unroll
        for (int rho = 0; rho < 4; rho++)
            av[rho] = *(const float4*)(A + (r + 8 * rho) * PITCH + 4 * k4);
        ulonglong2 bv[4][2];
        #pragma unroll
        for (int kp = 0; kp < 4; kp++) {
            bv[kp][0] = *(const ulonglong2*)(B + (4 * k4 + kp) * PITCH + 8 * c);
            bv[kp][1] = *(const ulonglong2*)(B + (4 * k4 + kp) * PITCH + 8 * c + 4);
        }
        #pragma unroll
        for (int rho = 0; rho < 4; rho++) {
            const float* af = (const float*)&av[rho];
            #pragma unroll
            for (int kp = 0; kp < 4; kp++) {
                const ull a2 = pk2(af[kp], af[kp]);
                acc[rho * 4 + 0] = fma2_(a2, bv[kp][0].x, acc[rho * 4 + 0]);
                acc[rho * 4 + 1] = fma2_(a2, bv[kp][0].y, acc[rho * 4 + 1]);
                acc[rho * 4 + 2] = fma2_(a2, bv[kp][1].x, acc[rho * 4 + 2]);
                acc[rho * 4 + 3] = fma2_(a2, bv[kp][1].y, acc[rho * 4 + 3]);
            }
        }
    }
}

__global__ __launch_bounds__(256, 2) void ring_main(const float* __restrict__ X,
                                                    float* __restrict__ out) {
    extern __shared__ float smem[];
    float* Wsm = smem;
    float* SL  = smem + OFF_SL;
    float* SR  = smem + OFF_SR;

    const int tid = threadIdx.x, w = tid >> 5, lane = tid & 31;
    const int r = lane >> 2, c = lane & 3;
    const int u = blockIdx.x >> 6;
    const int b0 = (blockIdx.x & 63) * 8;

    // W[b][p][c=(d0,d1)] = x[2p,d0] * x[2p+1,d1], straight from global X
    #pragma unroll
    for (int i = tid; i < 512; i += 256) {
        const int bb = i >> 6, pp = (i >> 4) & 3, cc = i & 15;
        Wsm[i] = X[(b0 + bb) * 32 + 8 * pp + (cc >> 2)] *
                 X[(b0 + bb) * 32 + 8 * pp + 4 + (cc & 3)];
    }
    __syncthreads();

    // ---- builds phase 1: S0 -> SL, S1 -> SR (normal orientation)
    build_stage<0>(u, 0, tid, Wsm, SL);
    build_stage<0>(u, 1, tid, Wsm, SR);
    __syncthreads();

    // ---- mm1: A = S0 @ S1, kept in registers
    ull acc1[16];
    mmk(SL + w * SLOT, SR + w * SLOT, r, c, acc1);
    __syncthreads();   // all warps done reading SL/SR

    // ---- builds phase 2: S2^T -> SL, S3^T -> SR (from g_KKT)
    build_stage<1>(u, 2, tid, Wsm, SL);
    build_stage<1>(u, 3, tid, Wsm, SR);
    __syncthreads();

    // ---- mm2: BT = S3^T @ S2^T = (S2 S3)^T ; out = sum A .* BT
    {
        ull acc2[16];
        mmk(SR + w * SLOT, SL + w * SLOT, r, c, acc2);
        ull t = 0ull;
        #pragma unroll
        for (int i = 0; i < 16; i++) t = fma2_(acc1[i], acc2[i], t);
        float tl, th; upk2(t, tl, th);
        float pacc = tl + th;
        #pragma unroll
        for (int o = 16; o; o >>= 1)
            pacc += __shfl_xor_sync(0xffffffffu, pacc, o);
        if (lane == 0) out[(b0 + w) * 64 + u] = pacc;
    }
}

extern "C" void kernel_launch(void* const* d_in, const int* in_sizes, int n_in,
                              void* d_out, int out_size) {
    const float* X = (const float*)d_in[0];
    const float* K = (const float*)d_in[1];
    if (in_sizes[0] != B_ * F_ * D_) {
        X = (const float*)d_in[1];
        K = (const float*)d_in[0];
    }
    const int pre_smem = (4224 + 4096 + 16 * 1056) * 4;
    cudaFuncSetAttribute(kk_precompute, cudaFuncAttributeMaxDynamicSharedMemorySize,
                         pre_smem);
    cudaFuncSetAttribute(ring_main, cudaFuncAttributeMaxDynamicSharedMemorySize,
                         SMEM_FLOATS * 4);
    kk_precompute<<<256, 512, pre_smem>>>(K);
    ring_main<<<64 * 64, 256, SMEM_FLOATS * 4>>>(X, (float*)d_out);
}

// round 14
// speedup vs baseline: 1.5505x; 1.0236x over previous
#include <cuda_runtime.h>

#define D_ 4
#define R_ 32
#define F_ 8
#define U_ 64
#define B_ 512

typedef unsigned long long ull;

// ---------- packed f32x2 helpers (SASS FFMA2) ----------
static __device__ __forceinline__ ull pk2(float lo, float hi) {
    ull r; asm("mov.b64 %0, {%1, %2};" : "=l"(r) : "f"(lo), "f"(hi)); return r;
}
static __device__ __forceinline__ void upk2(ull v, float& lo, float& hi) {
    asm("mov.b64 {%0, %1}, %2;" : "=f"(lo), "=f"(hi) : "l"(v));
}
static __device__ __forceinline__ ull fma2_(ull a, ull b, ull c) {
    ull d; asm("fma.rn.f32x2 %0, %1, %2, %3;" : "=l"(d) : "l"(a), "l"(b), "l"(c)); return d;
}
static __device__ __forceinline__ ull mul2_(ull a, ull b) {
    ull d; asm("mul.rn.f32x2 %0, %1, %2;" : "=l"(d) : "l"(a), "l"(b)); return d;
}
static __device__ __forceinline__ ull add2_(ull a, ull b) {
    ull d; asm("add.rn.f32x2 %0, %1, %2;" : "=l"(d) : "l"(a), "l"(b)); return d;
}

// Pair-merged products. Only the orientation each stage needs is materialized:
//   p in {0,1}: g_KK [u][p][c][j*32+k]   (row-major)
//   p in {2,3}: g_KKT[u][p][c][k*32+j]   (transposed)
__device__ float g_KK [U_ * 4 * 16 * 1024];   // 16 MB
__device__ float g_KKT[U_ * 4 * 16 * 1024];   // 16 MB

// ---------------------------------------------------------------------------
// Precompute: 128 blocks = (u-pair, p), 512 threads = 16 warps.
// u-pairing: staging loads are float2 across adjacent u (u is the contiguous
// dim of K) -> same sector count per instruction, 2x useful bytes, so the
// chip-wide scatter wavefronts halve. Warp w computes c = w for both u's.
// Smem: As[2][4][1056] | Bs[2][4][1024] | Ts[16][1056]  (~134 KB, no alias)
// ---------------------------------------------------------------------------
#define PAS 8448           // As floats (2 * 4 * 1056)
#define PBS 8192           // Bs floats (2 * 4 * 1024)
#define PRE_FLOATS (PAS + PBS + 16 * 1056)

__global__ __launch_bounds__(512) void kk_precompute(const float* __restrict__ K) {
    extern __shared__ float ps[];
    float* As = ps;                 // [uu][d][row*33+col]
    float* Bs = ps + PAS;           // [uu][d][e]
    float* Ts = ps + PAS + PBS;     // [warp][1056] transpose staging
    const int pr = blockIdx.x >> 2;        // u-pair 0..31
    const int p  = blockIdx.x & 3;
    const int u0 = pr * 2;
    const int tid = threadIdx.x;

    // stage both u's with float2 loads (u0 even -> 8B aligned)
    #pragma unroll
    for (int d = 0; d < 4; d++)
        #pragma unroll
        for (int e0 = 0; e0 < 1024; e0 += 512) {
            const int e = e0 + tid;
            const float2 va = *(const float2*)&K[((size_t)(d * 1024 + e) * 8 + 2 * p) * 64 + u0];
            const float2 vb = *(const float2*)&K[((size_t)(d * 1024 + e) * 8 + 2 * p + 1) * 64 + u0];
            const int ai = d * 1056 + (e >> 5) * 33 + (e & 31);
            As[ai]        = va.x;
            As[4224 + ai] = va.y;
            Bs[d * 1024 + e]        = vb.x;
            Bs[4096 + d * 1024 + e] = vb.y;
        }
    __syncthreads();

    const int c = tid >> 5, lane = tid & 31;
    const int d0 = c >> 2, d1 = c & 3;

    #pragma unroll 1
    for (int uu = 0; uu < 2; uu++) {
        ull acc[16];
        #pragma unroll
        for (int q = 0; q < 16; q++) acc[q] = 0ull;
        const float* arow = &As[uu * 4224 + d0 * 1056 + lane * 33];
        const ulonglong2* bmat = (const ulonglong2*)(Bs + uu * 4096 + d1 * 1024);
        #pragma unroll
        for (int j = 0; j < 32; j++) {
            const ull a2 = pk2(arow[j], arow[j]);
            #pragma unroll
            for (int q = 0; q < 8; q++) {
                const ulonglong2 bv = bmat[j * 8 + q];   // broadcast
                acc[2 * q]     = fma2_(a2, bv.x, acc[2 * q]);
                acc[2 * q + 1] = fma2_(a2, bv.y, acc[2 * q + 1]);
            }
        }
        float f[32];
        #pragma unroll
        for (int q = 0; q < 16; q++) upk2(acc[q], f[2 * q], f[2 * q + 1]);

        const int u = u0 + uu;
        if (p < 2) {
            // row-major write (lane = row), coalesced float4
            float4* dst = (float4*)(g_KK + (((u * 4 + p) * 16 + c) * 1024) + lane * 32);
            #pragma unroll
            for (int q = 0; q < 8; q++) {
                float4 o; o.x = f[4*q]; o.y = f[4*q+1]; o.z = f[4*q+2]; o.w = f[4*q+3];
                dst[q] = o;
            }
        } else {
            // transposed write via per-warp smem staging (pitch 33)
            float* Tw = Ts + c * 1056;
            #pragma unroll
            for (int k = 0; k < 32; k++) Tw[lane * 33 + k] = f[k];
            __syncwarp();
            float* kt = g_KKT + (((u * 4 + p) * 16 + c) * 1024);
            #pragma unroll
            for (int i = 0; i < 32; i++)
                kt[i * 32 + lane] = Tw[lane * 33 + i];   // coalesced STG.32
            __syncwarp();   // Tw reuse safe for uu=1
        }
    }
}

// ---------------------------------------------------------------------------
// Main (UNCHANGED from the proven R13 version, 193.6 us).
// Block = 256 threads = 8 warps, one u, 8 b (warp w owns b = b0+w).
// Smem (floats): W[512] | SL[8*1152] | SR[8*1152]   (~74 KB, 2 CTAs/SM)
// out = sum_{i,j} A[i,j] * BT[i,j],  A = S0@S1 (regs), BT = S3T@S2T (regs).
// ---------------------------------------------------------------------------
#define PITCH 36
#define SLOT  1152
#define OFF_SL  512
#define OFF_SR  (OFF_SL + 8 * SLOT)
#define SMEM_FLOATS (OFF_SR + 8 * SLOT)

template <int T>
static __device__ __forceinline__ void build_stage(int u, int p, int e,
                                                   const float* Wsm, float* dst) {
    const ulonglong2* base = (const ulonglong2*)(
        (T ? g_KKT : g_KK) + (size_t)((u * 4 + p) * 16) * 1024);
    ull acc[8][2];
    #pragma unroll
    for (int h = 0; h < 2; h++) {
        ulonglong2 kk[8];
        #pragma unroll
        for (int cc = 0; cc < 8; cc++) kk[cc] = base[(h * 8 + cc) * 256 + e];
        #pragma unroll
        for (int b = 0; b < 8; b++) {
            const float4* wp = (const float4*)(Wsm + (b * 4 + p) * 16 + h * 8);
            const float4 wa = wp[0], wb = wp[1];     // broadcast
            const ull q0 = pk2(wa.x, wa.x), q1 = pk2(wa.y, wa.y);
            const ull q2 = pk2(wa.z, wa.z), q3 = pk2(wa.w, wa.w);
            const ull q4 = pk2(wb.x, wb.x), q5 = pk2(wb.y, wb.y);
            const ull q6 = pk2(wb.z, wb.z), q7 = pk2(wb.w, wb.w);
            ull ax0 = mul2_(q0, kk[0].x), ay0 = mul2_(q0, kk[0].y);
            ull ax1 = mul2_(q1, kk[1].x), ay1 = mul2_(q1, kk[1].y);
            ax0 = fma2_(q2, kk[2].x, ax0);  ay0 = fma2_(q2, kk[2].y, ay0);
            ax1 = fma2_(q3, kk[3].x, ax1);  ay1 = fma2_(q3, kk[3].y, ay1);
            ax0 = fma2_(q4, kk[4].x, ax0);  ay0 = fma2_(q4, kk[4].y, ay0);
            ax1 = fma2_(q5, kk[5].x, ax1);  ay1 = fma2_(q5, kk[5].y, ay1);
            ax0 = fma2_(q6, kk[6].x, ax0);  ay0 = fma2_(q6, kk[6].y, ay0);
            ax1 = fma2_(q7, kk[7].x, ax1);  ay1 = fma2_(q7, kk[7].y, ay1);
            const ull sx = add2_(ax0, ax1), sy = add2_(ay0, ay1);
            if (h == 0) { acc[b][0] = sx; acc[b][1] = sy; }
            else { acc[b][0] = add2_(acc[b][0], sx); acc[b][1] = add2_(acc[b][1], sy); }
        }
    }
    const int j = e >> 3, k4 = e & 7;
    #pragma unroll
    for (int b = 0; b < 8; b++) {
        float4 o;
        upk2(acc[b][0], o.x, o.y); upk2(acc[b][1], o.z, o.w);
        *(float4*)(dst + b * SLOT + j * PITCH + 4 * k4) = o;
    }
}

static __device__ __forceinline__ void mmk(const float* A, const float* B,
                                           int r, int c, ull acc[16]) {
    #pragma unroll
    for (int i = 0; i < 16; i++) acc[i] = 0ull;
    #pragma unroll
    for (int k4 = 0; k4 < 8; k4++) {
        float4 av[4];
        #pragma unroll
        for (int rho = 0; rho < 4; rho++)
            av[rho] = *(const float4*)(A + (r + 8 * rho) * PITCH + 4 * k4);
        ulonglong2 bv[4][2];
        #pragma unroll
        for (int kp = 0; kp < 4; kp++) {
            bv[kp][0] = *(const ulonglong2*)(B + (4 * k4 + kp) * PITCH + 8 * c);
            bv[kp][1] = *(const ulonglong2*)(B + (4 * k4 + kp) * PITCH + 8 * c + 4);
        }
        #pragma unroll
        for (int rho = 0; rho < 4; rho++) {
            const float* af = (const float*)&av[rho];
            #pragma unroll
            for (int kp = 0; kp < 4; kp++) {
                const ull a2 = pk2(af[kp], af[kp]);
                acc[rho * 4 + 0] = fma2_(a2, bv[kp][0].x, acc[rho * 4 + 0]);
                acc[rho * 4 + 1] = fma2_(a2, bv[kp][0].y, acc[rho * 4 + 1]);
                acc[rho * 4 + 2] = fma2_(a2, bv[kp][1].x, acc[rho * 4 + 2]);
                acc[rho * 4 + 3] = fma2_(a2, bv[kp][1].y, acc[rho * 4 + 3]);
            }
        }
    }
}

__global__ __launch_bounds__(256, 2) void ring_main(const float* __restrict__ X,
                                                    float* __restrict__ out) {
    extern __shared__ float smem[];
    float* Wsm = smem;
    float* SL  = smem + OFF_SL;
    float* SR  = smem + OFF_SR;

    const int tid = threadIdx.x, w = tid >> 5, lane = tid & 31;
    const int r = lane >> 2, c = lane & 3;
    const int u = blockIdx.x >> 6;
    const int b0 = (blockIdx.x & 63) * 8;

    // W[b][p][c=(d0,d1)] = x[2p,d0] * x[2p+1,d1], straight from global X
    #pragma unroll
    for (int i = tid; i < 512; i += 256) {
        const int bb = i >> 6, pp = (i >> 4) & 3, cc = i & 15;
        Wsm[i] = X[(b0 + bb) * 32 + 8 * pp + (cc >> 2)] *
                 X[(b0 + bb) * 32 + 8 * pp + 4 + (cc & 3)];
    }
    __syncthreads();

    // ---- builds phase 1: S0 -> SL, S1 -> SR (normal orientation)
    build_stage<0>(u, 0, tid, Wsm, SL);
    build_stage<0>(u, 1, tid, Wsm, SR);
    __syncthreads();

    // ---- mm1: A = S0 @ S1, kept in registers
    ull acc1[16];
    mmk(SL + w * SLOT, SR + w * SLOT, r, c, acc1);
    __syncthreads();   // all warps done reading SL/SR

    // ---- builds phase 2: S2^T -> SL, S3^T -> SR (from g_KKT)
    build_stage<1>(u, 2, tid, Wsm, SL);
    build_stage<1>(u, 3, tid, Wsm, SR);
    __syncthreads();

    // ---- mm2: BT = S3^T @ S2^T = (S2 S3)^T ; out = sum A .* BT
    {
        ull acc2[16];
        mmk(SR + w * SLOT, SL + w * SLOT, r, c, acc2);
        ull t = 0ull;
        #pragma unroll
        for (int i = 0; i < 16; i++) t = fma2_(acc1[i], acc2[i], t);
        float tl, th; upk2(t, tl, th);
        float pacc = tl + th;
        #pragma unroll
        for (int o = 16; o; o >>= 1)
            pacc += __shfl_xor_sync(0xffffffffu, pacc, o);
        if (lane == 0) out[(b0 + w) * 64 + u] = pacc;
    }
}

extern "C" void kernel_launch(void* const* d_in, const int* in_sizes, int n_in,
                              void* d_out, int out_size) {
    const float* X = (const float*)d_in[0];
    const float* K = (const float*)d_in[1];
    if (in_sizes[0] != B_ * F_ * D_) {
        X = (const float*)d_in[1];
        K = (const float*)d_in[0];
    }
    const int pre_smem = PRE_FLOATS * 4;
    cudaFuncSetAttribute(kk_precompute, cudaFuncAttributeMaxDynamicSharedMemorySize,
                         pre_smem);
    cudaFuncSetAttribute(ring_main, cudaFuncAttributeMaxDynamicSharedMemorySize,
                         SMEM_FLOATS * 4);
    kk_precompute<<<128, 512, pre_smem>>>(K);
    ring_main<<<64 * 64, 256, SMEM_FLOATS * 4>>>(X, (float*)d_out);
}

// round 16
// speedup vs baseline: 1.5845x; 1.0220x over previous
#include <cuda_runtime.h>

#define D_ 4
#define R_ 32
#define F_ 8
#define U_ 64
#define B_ 512

typedef unsigned long long ull;

// ---------- packed f32x2 helpers (SASS FFMA2) ----------
static __device__ __forceinline__ ull pk2(float lo, float hi) {
    ull r; asm("mov.b64 %0, {%1, %2};" : "=l"(r) : "f"(lo), "f"(hi)); return r;
}
static __device__ __forceinline__ void upk2(ull v, float& lo, float& hi) {
    asm("mov.b64 {%0, %1}, %2;" : "=f"(lo), "=f"(hi) : "l"(v));
}
static __device__ __forceinline__ ull fma2_(ull a, ull b, ull c) {
    ull d; asm("fma.rn.f32x2 %0, %1, %2, %3;" : "=l"(d) : "l"(a), "l"(b), "l"(c)); return d;
}
static __device__ __forceinline__ ull mul2_(ull a, ull b) {
    ull d; asm("mul.rn.f32x2 %0, %1, %2;" : "=l"(d) : "l"(a), "l"(b)); return d;
}
static __device__ __forceinline__ ull add2_(ull a, ull b) {
    ull d; asm("add.rn.f32x2 %0, %1, %2;" : "=l"(d) : "l"(a), "l"(b)); return d;
}

// Pair-merged products. Only the orientation each stage needs is materialized:
//   p in {0,1}: g_KK [u][p][c][j*32+k]   (row-major)
//   p in {2,3}: g_KKT[u][p][c][k*32+j]   (transposed)
__device__ float g_KK [U_ * 4 * 16 * 1024];   // 16 MB
__device__ float g_KKT[U_ * 4 * 16 * 1024];   // 16 MB

#define PITCH 36

// Register-tiled 32x32x32 matmul: C = A @ B, operands pitch-36 in smem.
// Lane (r = lane>>2, c = lane&3): rows {r,r+8,r+16,r+24} x cols {8c..8c+7}.
// Shared by main kernel and precompute.
static __device__ __forceinline__ void mmk(const float* A, const float* B,
                                           int r, int c, ull acc[16]) {
    #pragma unroll
    for (int i = 0; i < 16; i++) acc[i] = 0ull;
    #pragma unroll
    for (int k4 = 0; k4 < 8; k4++) {
        float4 av[4];
        #pragma unroll
        for (int rho = 0; rho < 4; rho++)
            av[rho] = *(const float4*)(A + (r + 8 * rho) * PITCH + 4 * k4);
        ulonglong2 bv[4][2];
        #pragma unroll
        for (int kp = 0; kp < 4; kp++) {
            bv[kp][0] = *(const ulonglong2*)(B + (4 * k4 + kp) * PITCH + 8 * c);
            bv[kp][1] = *(const ulonglong2*)(B + (4 * k4 + kp) * PITCH + 8 * c + 4);
        }
        #pragma unroll
        for (int rho = 0; rho < 4; rho++) {
            const float* af = (const float*)&av[rho];
            #pragma unroll
            for (int kp = 0; kp < 4; kp++) {
                const ull a2 = pk2(af[kp], af[kp]);
                acc[rho * 4 + 0] = fma2_(a2, bv[kp][0].x, acc[rho * 4 + 0]);
                acc[rho * 4 + 1] = fma2_(a2, bv[kp][0].y, acc[rho * 4 + 1]);
                acc[rho * 4 + 2] = fma2_(a2, bv[kp][1].x, acc[rho * 4 + 2]);
                acc[rho * 4 + 3] = fma2_(a2, bv[kp][1].y, acc[rho * 4 + 3]);
            }
        }
    }
}

// ---------------------------------------------------------------------------
// Precompute: 128 blocks = (u-pair, p), 512 threads = 16 warps; warp w
// computes c = w for both u's of the pair. float2 staging across adjacent u
// (halves scatter wavefronts); operands staged pitch-36 so the register-tiled
// mmk (96 LDS/matmul instead of ~544) computes each 32x32x32 product.
// Smem (floats): As[2][4][1152] | Bs[2][4][1152] | Ts[16][1056]  (~141 KB)
// ---------------------------------------------------------------------------
#define PAS 9216           // 2 * 4 * 1152
#define PRE_FLOATS (2 * PAS + 16 * 1056)

__global__ __launch_bounds__(512) void kk_precompute(const float* __restrict__ K) {
    extern __shared__ float ps[];
    float* As = ps;                 // [uu][d][row*36+col]
    float* Bs = ps + PAS;           // [uu][d][row*36+col]
    float* Ts = ps + 2 * PAS;       // [warp][1056] transpose staging (pitch 33)
    const int pr = blockIdx.x >> 2;        // u-pair 0..31
    const int p  = blockIdx.x & 3;
    const int u0 = pr * 2;
    const int tid = threadIdx.x;

    // stage both u's with float2 loads (u0 even -> 8B aligned)
    #pragma unroll
    for (int d = 0; d < 4; d++)
        #pragma unroll
        for (int e0 = 0; e0 < 1024; e0 += 512) {
            const int e = e0 + tid;
            const float2 va = *(const float2*)&K[((size_t)(d * 1024 + e) * 8 + 2 * p) * 64 + u0];
            const float2 vb = *(const float2*)&K[((size_t)(d * 1024 + e) * 8 + 2 * p + 1) * 64 + u0];
            const int idx = d * 1152 + (e >> 5) * PITCH + (e & 31);
            As[idx]        = va.x;
            As[4608 + idx] = va.y;
            Bs[idx]        = vb.x;
            Bs[4608 + idx] = vb.y;
        }
    __syncthreads();

    const int w = tid >> 5, lane = tid & 31;
    const int r = lane >> 2, cc = lane & 3;
    const int d0 = w >> 2, d1 = w & 3;

    #pragma unroll 1
    for (int uu = 0; uu < 2; uu++) {
        ull acc[16];
        mmk(As + uu * 4608 + d0 * 1152, Bs + uu * 4608 + d1 * 1152, r, cc, acc);

        const int u = u0 + uu;
        if (p < 2) {
            // row-major write: lane (r,cc), rows {r+8rho}, cols {8cc..8cc+7}
            float* dst = g_KK + (((u * 4 + p) * 16 + w) * 1024);
            #pragma unroll
            for (int rho = 0; rho < 4; rho++) {
                float4 o0, o1;
                upk2(acc[rho * 4 + 0], o0.x, o0.y); upk2(acc[rho * 4 + 1], o0.z, o0.w);
                upk2(acc[rho * 4 + 2], o1.x, o1.y); upk2(acc[rho * 4 + 3], o1.z, o1.w);
                *(float4*)(dst + (r + 8 * rho) * 32 + 8 * cc)     = o0;
                *(float4*)(dst + (r + 8 * rho) * 32 + 8 * cc + 4) = o1;
            }
        } else {
            // transposed write via per-warp Ts staging: Ts[k*33+j] = C[j][k]
            float* Tw = Ts + w * 1056;
            #pragma unroll
            for (int rho = 0; rho < 4; rho++) {
                const int row = r + 8 * rho;
                #pragma unroll
                for (int gp = 0; gp < 4; gp++) {
                    float lo, hi;
                    upk2(acc[rho * 4 + gp], lo, hi);
                    Tw[(8 * cc + 2 * gp) * 33 + row]     = lo;   // bank-distinct
                    Tw[(8 * cc + 2 * gp + 1) * 33 + row] = hi;
                }
            }
            __syncwarp();
            float* kt = g_KKT + (((u * 4 + p) * 16 + w) * 1024);
            #pragma unroll
            for (int i = 0; i < 32; i++)
                kt[i * 32 + lane] = Tw[i * 33 + lane];   // coalesced STG.32
            __syncwarp();   // Tw reuse safe for uu=1
        }
    }
}

// ---------------------------------------------------------------------------
// Main (UNCHANGED from the proven R13/R14 version, 195.4 us).
// Block = 256 threads = 8 warps, one u, 8 b (warp w owns b = b0+w).
// Smem (floats): W[512] | SL[8*1152] | SR[8*1152]   (~74 KB, 2 CTAs/SM)
// out = sum_{i,j} A[i,j] * BT[i,j],  A = S0@S1 (regs), BT = S3T@S2T (regs).
// ---------------------------------------------------------------------------
#define SLOT  1152
#define OFF_SL  512
#define OFF_SR  (OFF_SL + 8 * SLOT)
#define SMEM_FLOATS (OFF_SR + 8 * SLOT)

template <int T>
static __device__ __forceinline__ void build_stage(int u, int p, int e,
                                                   const float* Wsm, float* dst) {
    const ulonglong2* base = (const ulonglong2*)(
        (T ? g_KKT : g_KK) + (size_t)((u * 4 + p) * 16) * 1024);
    ull acc[8][2];
    #pragma unroll
    for (int h = 0; h < 2; h++) {
        ulonglong2 kk[8];
        #pragma unroll
        for (int cc = 0; cc < 8; cc++) kk[cc] = base[(h * 8 + cc) * 256 + e];
        #pragma unroll
        for (int b = 0; b < 8; b++) {
            const float4* wp = (const float4*)(Wsm + (b * 4 + p) * 16 + h * 8);
            const float4 wa = wp[0], wb = wp[1];     // broadcast
            const ull q0 = pk2(wa.x, wa.x), q1 = pk2(wa.y, wa.y);
            const ull q2 = pk2(wa.z, wa.z), q3 = pk2(wa.w, wa.w);
            const ull q4 = pk2(wb.x, wb.x), q5 = pk2(wb.y, wb.y);
            const ull q6 = pk2(wb.z, wb.z), q7 = pk2(wb.w, wb.w);
            ull ax0 = mul2_(q0, kk[0].x), ay0 = mul2_(q0, kk[0].y);
            ull ax1 = mul2_(q1, kk[1].x), ay1 = mul2_(q1, kk[1].y);
            ax0 = fma2_(q2, kk[2].x, ax0);  ay0 = fma2_(q2, kk[2].y, ay0);
            ax1 = fma2_(q3, kk[3].x, ax1);  ay1 = fma2_(q3, kk[3].y, ay1);
            ax0 = fma2_(q4, kk[4].x, ax0);  ay0 = fma2_(q4, kk[4].y, ay0);
            ax1 = fma2_(q5, kk[5].x, ax1);  ay1 = fma2_(q5, kk[5].y, ay1);
            ax0 = fma2_(q6, kk[6].x, ax0);  ay0 = fma2_(q6, kk[6].y, ay0);
            ax1 = fma2_(q7, kk[7].x, ax1);  ay1 = fma2_(q7, kk[7].y, ay1);
            const ull sx = add2_(ax0, ax1), sy = add2_(ay0, ay1);
            if (h == 0) { acc[b][0] = sx; acc[b][1] = sy; }
            else { acc[b][0] = add2_(acc[b][0], sx); acc[b][1] = add2_(acc[b][1], sy); }
        }
    }
    const int j = e >> 3, k4 = e & 7;
    #pragma unroll
    for (int b = 0; b < 8; b++) {
        float4 o;
        upk2(acc[b][0], o.x, o.y); upk2(acc[b][1], o.z, o.w);
        *(float4*)(dst + b * SLOT + j * PITCH + 4 * k4) = o;
    }
}

__global__ __launch_bounds__(256, 2) void ring_main(const float* __restrict__ X,
                                                    float* __restrict__ out) {
    extern __shared__ float smem[];
    float* Wsm = smem;
    float* SL  = smem + OFF_SL;
    float* SR  = smem + OFF_SR;

    const int tid = threadIdx.x, w = tid >> 5, lane = tid & 31;
    const int r = lane >> 2, c = lane & 3;
    const int u = blockIdx.x >> 6;
    const int b0 = (blockIdx.x & 63) * 8;

    // W[b][p][c=(d0,d1)] = x[2p,d0] * x[2p+1,d1], straight from global X
    #pragma unroll
    for (int i = tid; i < 512; i += 256) {
        const int bb = i >> 6, pp = (i >> 4) & 3, cc = i & 15;
        Wsm[i] = X[(b0 + bb) * 32 + 8 * pp + (cc >> 2)] *
                 X[(b0 + bb) * 32 + 8 * pp + 4 + (cc & 3)];
    }
    __syncthreads();

    // ---- builds phase 1: S0 -> SL, S1 -> SR (normal orientation)
    build_stage<0>(u, 0, tid, Wsm, SL);
    build_stage<0>(u, 1, tid, Wsm, SR);
    __syncthreads();

    // ---- mm1: A = S0 @ S1, kept in registers
    ull acc1[16];
    mmk(SL + w * SLOT, SR + w * SLOT, r, c, acc1);
    __syncthreads();   // all warps done reading SL/SR

    // ---- builds phase 2: S2^T -> SL, S3^T -> SR (from g_KKT)
    build_stage<1>(u, 2, tid, Wsm, SL);
    build_stage<1>(u, 3, tid, Wsm, SR);
    __syncthreads();

    // ---- mm2: BT = S3^T @ S2^T = (S2 S3)^T ; out = sum A .* BT
    {
        ull acc2[16];
        mmk(SR + w * SLOT, SL + w * SLOT, r, c, acc2);
        ull t = 0ull;
        #pragma unroll
        for (int i = 0; i < 16; i++) t = fma2_(acc1[i], acc2[i], t);
        float tl, th; upk2(t, tl, th);
        float pacc = tl + th;
        #pragma unroll
        for (int o = 16; o; o >>= 1)
            pacc += __shfl_xor_sync(0xffffffffu, pacc, o);
        if (lane == 0) out[(b0 + w) * 64 + u] = pacc;
    }
}

extern "C" void kernel_launch(void* const* d_in, const int* in_sizes, int n_in,
                              void* d_out, int out_size) {
    const float* X = (const float*)d_in[0];
    const float* K = (const float*)d_in[1];
    if (in_sizes[0] != B_ * F_ * D_) {
        X = (const float*)d_in[1];
        K = (const float*)d_in[0];
    }
    const int pre_smem = PRE_FLOATS * 4;
    cudaFuncSetAttribute(kk_precompute, cudaFuncAttributeMaxDynamicSharedMemorySize,
                         pre_smem);
    cudaFuncSetAttribute(ring_main, cudaFuncAttributeMaxDynamicSharedMemorySize,
                         SMEM_FLOATS * 4);
    kk_precompute<<<128, 512, pre_smem>>>(K);
    ring_main<<<64 * 64, 256, SMEM_FLOATS * 4>>>(X, (float*)d_out);
}